// round 16
// baseline (speedup 1.0000x reference)
#include <cuda_runtime.h>
#include <cuda_fp16.h>
#include <math_constants.h>
#include <cstdint>

#define BATCH 8
#define SEQ   1024
#define DMODEL 768
#define NH    12
#define HDIM  64
#define IMG   32            // sqrt(SEQ)
#define TABLE 3969          // (2*IMG-1)^2
#define DD    (DMODEL*DMODEL)
#define LOG2E 1.44269504f

// ---------------- scratch (device globals: no allocation allowed) ----------
__device__ __half g_hAq [BATCH*SEQ*DMODEL];
__device__ __half g_hAkv[BATCH*SEQ*DMODEL];
__device__ __half g_hW  [4*DD];                 // Wq, Wk, Wv, Wo
__device__ __half g_Qh[BATCH*NH*SEQ*HDIM];
__device__ __half g_Kh[BATCH*NH*SEQ*HDIM];
__device__ __half g_Vh[BATCH*NH*SEQ*HDIM];
__device__ __half g_Xh[BATCH*SEQ*DMODEL];
__device__ float  g_biasT[NH*TABLE];            // rel_bias transposed: [H][TABLE]
__device__ __half g_biasH[(size_t)NH*SEQ*SEQ];  // dense bias*log2e: [H][Sq][Sk] (25 MB)

// ---------------- helpers --------------------------------------------------
__device__ __forceinline__ unsigned h2u(__half2 h) { return *(unsigned*)&h; }
__device__ __forceinline__ uint2 f4_to_h4(float4 v) {
    uint2 r;
    r.x = h2u(__floats2half2_rn(v.x, v.y));
    r.y = h2u(__floats2half2_rn(v.z, v.w));
    return r;
}
__device__ __forceinline__ float fexp2(float x) {
    float y; asm("ex2.approx.f32 %0, %1;" : "=f"(y) : "f"(x)); return y;
}

__device__ __forceinline__ void mma_f16(float* d, const unsigned* a, const unsigned* b) {
    asm volatile("mma.sync.aligned.m16n8k16.row.col.f32.f16.f16.f32 "
        "{%0,%1,%2,%3},{%4,%5,%6,%7},{%8,%9},{%0,%1,%2,%3};"
        : "+f"(d[0]), "+f"(d[1]), "+f"(d[2]), "+f"(d[3])
        : "r"(a[0]), "r"(a[1]), "r"(a[2]), "r"(a[3]),
          "r"(b[0]), "r"(b[1]));
}

__device__ __forceinline__ void ldsm_x4(unsigned& r0, unsigned& r1, unsigned& r2, unsigned& r3,
                                        unsigned addr) {
    asm volatile("ldmatrix.sync.aligned.m8n8.x4.shared.b16 {%0,%1,%2,%3}, [%4];"
        : "=r"(r0), "=r"(r1), "=r"(r2), "=r"(r3) : "r"(addr));
}
__device__ __forceinline__ void ldsm_x4_t(unsigned& r0, unsigned& r1, unsigned& r2, unsigned& r3,
                                          unsigned addr) {
    asm volatile("ldmatrix.sync.aligned.m8n8.x4.trans.shared.b16 {%0,%1,%2,%3}, [%4];"
        : "=r"(r0), "=r"(r1), "=r"(r2), "=r"(r3) : "r"(addr));
}

__device__ __forceinline__ void cp16(unsigned dst, const void* src) {
    asm volatile("cp.async.cg.shared.global [%0], [%1], 16;" :: "r"(dst), "l"(src) : "memory");
}
#define CP_COMMIT() asm volatile("cp.async.commit_group;" ::: "memory")
#define CP_WAIT0()  asm volatile("cp.async.wait_group 0;" ::: "memory")

// ---------------- conversion kernels ---------------------------------------
__global__ void transpose_bias(const float* __restrict__ rb) {
    int i = blockIdx.x * blockDim.x + threadIdx.x;
    if (i < TABLE * NH) {
        int t = i / NH, h = i % NH;
        g_biasT[h * TABLE + t] = rb[i];
    }
}

// dense bias expansion (scaled by log2e for exp2 softmax):
// g_biasH[h][q][k] = log2e * table[h][(qy-ky+31)*63 + (qx-kx+31)]
// one thread writes 8 halves (k..k+7). For k aligned to 8, kx ≤ 24 so the
// 8-span stays in one ky row; ridx decreases by 1 per k.
__global__ void bias_expand() {
    int idx = blockIdx.x * blockDim.x + threadIdx.x;
    const int NK8 = SEQ / 8;
    if (idx >= NH * SEQ * NK8) return;
    int k8 = idx % NK8;
    int q  = (idx / NK8) % SEQ;
    int h  = idx / (NK8 * SEQ);
    int k  = k8 * 8;
    int qy = q >> 5, qx = q & 31, ky = k >> 5, kx = k & 31;
    int ridx = (qy - ky + (IMG - 1)) * (2 * IMG - 1) + (qx - kx + (IMG - 1));
    const float* t = g_biasT + h * TABLE + ridx;
    uint4 u;
    u.x = h2u(__floats2half2_rn(t[0]  * LOG2E, t[-1] * LOG2E));
    u.y = h2u(__floats2half2_rn(t[-2] * LOG2E, t[-3] * LOG2E));
    u.z = h2u(__floats2half2_rn(t[-4] * LOG2E, t[-5] * LOG2E));
    u.w = h2u(__floats2half2_rn(t[-6] * LOG2E, t[-7] * LOG2E));
    *(uint4*)&g_biasH[((size_t)h * SEQ + q) * SEQ + k] = u;
}

__global__ void f2h_inputs(const float* __restrict__ s0, const float* __restrict__ s1, int n4) {
    int i = blockIdx.x * blockDim.x + threadIdx.x;
    const float* s = blockIdx.y ? s1 : s0;
    __half* d = blockIdx.y ? g_hAkv : g_hAq;
    if (i < n4) *((uint2*)d + i) = f4_to_h4(*((const float4*)s + i));
}

__global__ void f2h_weights(const float* __restrict__ s0, const float* __restrict__ s1,
                            const float* __restrict__ s2, const float* __restrict__ s3) {
    int i = blockIdx.x * blockDim.x + threadIdx.x;
    const float* s = (blockIdx.y == 0) ? s0 : (blockIdx.y == 1) ? s1 : (blockIdx.y == 2) ? s2 : s3;
    __half* d = g_hW + (size_t)blockIdx.y * DD;
    const int n4 = DD / 4;
    if (i < n4) *((uint2*)d + i) = f4_to_h4(*((const float4*)s + i));
}

// ---------------- FP16 GEMM, 128x128 tile, 256 thr, cp.async double-buffer -
// mode 0 (QKV): grid.y = 18; y/6 selects Q/K/V (writes half head-major).
//               Q scale folds log2e for the exp2 softmax downstream.
// mode 1 (out): grid.y = 6; A = g_Xh, writes f32 outPlain.
__global__ void __launch_bounds__(256) gemm128(
    const float* __restrict__ c0, const float* __restrict__ c1, const float* __restrict__ c2,
    float* __restrict__ outPlain, int mode)
{
    const int N = DMODEL, K = DMODEL;
    __shared__ __align__(16) __half As[2][128][40];
    __shared__ __align__(16) __half Bs[2][32][136];

    const __half* A; const __half* W; const float* bias;
    __half* outH; float scale; int ybase;
    if (mode == 0) {
        int sel = blockIdx.y / 6; ybase = blockIdx.y % 6;
        A    = (sel == 0) ? g_hAq : g_hAkv;
        W    = g_hW + (size_t)sel * DD;
        bias = (sel == 0) ? c0 : (sel == 1) ? c1 : c2;
        outH = (sel == 0) ? g_Qh : (sel == 1) ? g_Kh : g_Vh;
        scale = (sel == 0) ? (0.125f * LOG2E) : 1.0f;
    } else {
        ybase = blockIdx.y;
        A = g_Xh; W = g_hW + (size_t)3 * DD; bias = c0;
        outH = nullptr; scale = 1.0f;
    }

    int m0 = blockIdx.x * 128, n0 = ybase * 128;
    int tid  = threadIdx.x;
    int lane = tid & 31, warp = tid >> 5;
    int g = lane >> 2, t4 = lane & 3;
    int wm = (warp >> 1) * 32, wn = (warp & 1) * 64;

    unsigned sA = (unsigned)__cvta_generic_to_shared(&As[0][0][0]);
    unsigned sB = (unsigned)__cvta_generic_to_shared(&Bs[0][0][0]);

    int aRowL = (lane & 7) + ((lane & 8) ? 8 : 0);
    int aColL = (lane & 16) ? 8 : 0;
    int bRowL = (lane & 7) + ((lane & 8) ? 8 : 0);
    int bColL = (lane & 16) ? 8 : 0;

    float acc[2][8][4];
    #pragma unroll
    for (int i = 0; i < 2; i++)
        #pragma unroll
        for (int j = 0; j < 8; j++)
            #pragma unroll
            for (int r = 0; r < 4; r++) acc[i][j][r] = 0.f;

    int aSRow[2], aSCol[2], bSRow[2], bSCol[2];
    #pragma unroll
    for (int j = 0; j < 2; j++) {
        int idx = tid + j * 256;
        aSRow[j] = idx >> 2;  aSCol[j] = (idx & 3) * 8;
        bSRow[j] = idx >> 4;  bSCol[j] = (idx & 15) * 8;
    }

    auto stage = [&](int buf, int k0) {
        #pragma unroll
        for (int j = 0; j < 2; j++)
            cp16(sA + ((buf*128 + aSRow[j]) * 40 + aSCol[j]) * 2,
                 A + (size_t)(m0 + aSRow[j]) * K + k0 + aSCol[j]);
        #pragma unroll
        for (int j = 0; j < 2; j++)
            cp16(sB + ((buf*32 + bSRow[j]) * 136 + bSCol[j]) * 2,
                 W + (size_t)(k0 + bSRow[j]) * N + n0 + bSCol[j]);
        CP_COMMIT();
    };

    stage(0, 0);

    const int NCHUNK = K / 32;                 // 24
    for (int kc = 0; kc < NCHUNK; kc++) {
        int cur = kc & 1;
        CP_WAIT0();
        __syncthreads();
        if (kc + 1 < NCHUNK) stage(cur ^ 1, (kc + 1) * 32);

        #pragma unroll
        for (int ks = 0; ks < 2; ks++) {
            unsigned a[2][4];
            #pragma unroll
            for (int mf = 0; mf < 2; mf++) {
                unsigned addr = sA + ((cur*128 + wm + mf*16 + aRowL) * 40 + ks*16 + aColL) * 2;
                ldsm_x4(a[mf][0], a[mf][1], a[mf][2], a[mf][3], addr);
            }
            #pragma unroll
            for (int nfp = 0; nfp < 4; nfp++) {
                unsigned b0, b1, b2, b3;
                unsigned addr = sB + ((cur*32 + ks*16 + bRowL) * 136 + wn + nfp*16 + bColL) * 2;
                ldsm_x4_t(b0, b1, b2, b3, addr);
                unsigned bb0[2] = { b0, b1 }, bb1[2] = { b2, b3 };
                #pragma unroll
                for (int mf = 0; mf < 2; mf++) {
                    mma_f16(acc[mf][nfp*2    ], a[mf], bb0);
                    mma_f16(acc[mf][nfp*2 + 1], a[mf], bb1);
                }
            }
        }
    }

    // epilogue (c-layout: rows g/g+8, cols 2t4,2t4+1)
    #pragma unroll
    for (int mf = 0; mf < 2; mf++) {
        #pragma unroll
        for (int nf = 0; nf < 8; nf++) {
            #pragma unroll
            for (int rr = 0; rr < 2; rr++) {
                int m = m0 + wm + mf*16 + g + (rr ? 8 : 0);
                int n = n0 + wn + nf*8 + t4*2;
                float vx = (acc[mf][nf][rr*2    ] + bias[n    ]) * scale;
                float vy = (acc[mf][nf][rr*2 + 1] + bias[n + 1]) * scale;
                if (mode == 0) {
                    int b_ = m >> 10, s_ = m & 1023, h_ = n >> 6, hd = n & 63;
                    *(unsigned*)&outH[(((size_t)(b_ * NH + h_)) * SEQ + s_) * HDIM + hd] =
                        h2u(__floats2half2_rn(vx, vy));
                } else {
                    float2 v = { vx, vy };
                    *(float2*)&outPlain[(size_t)m * N + n] = v;
                }
            }
        }
    }
}

// ---------------- FP16 flash attention, exp2 softmax, 2 CTAs/SM -------------
// grid (SEQ/128, BATCH*NH), 256 thr; 8 warps x 16 q rows. cp.async K/V
// double-buffer; dense half bias (pre-scaled by log2e). min-blocks=2 caps
// regs at 124 -> 2 CTAs/SM for latency hiding.
__global__ void __launch_bounds__(256, 2) attn_kernel()
{
    __shared__ __align__(16) __half Ks[2][64][72];
    __shared__ __align__(16) __half Vs[2][64][72];

    int bh = blockIdx.y;
    int b_ = bh / NH, h_ = bh % NH;
    int q0 = blockIdx.x * 128;
    int tid = threadIdx.x, lane = tid & 31, warp = tid >> 5;
    int g = lane >> 2, t4 = lane & 3;

    const __half* Qb = g_Qh + (size_t)bh * SEQ * HDIM;
    const __half* Kb = g_Kh + (size_t)bh * SEQ * HDIM;
    const __half* Vb = g_Vh + (size_t)bh * SEQ * HDIM;

    unsigned sK = (unsigned)__cvta_generic_to_shared(&Ks[0][0][0]);
    unsigned sV = (unsigned)__cvta_generic_to_shared(&Vs[0][0][0]);

    int qi0 = q0 + warp * 16 + g;
    int qi1 = qi0 + 8;

    const __half* bQ0 = g_biasH + ((size_t)h_ * SEQ + qi0) * SEQ + t4 * 2;
    const __half* bQ1 = g_biasH + ((size_t)h_ * SEQ + qi1) * SEQ + t4 * 2;

    // Q a-frags (4 ksteps x 4 regs), half2 loads from gmem
    unsigned qa[4][4];
    #pragma unroll
    for (int ks = 0; ks < 4; ks++) {
        qa[ks][0] = *(const unsigned*)(Qb + (size_t)qi0 * HDIM + ks*16 + 2*t4);
        qa[ks][1] = *(const unsigned*)(Qb + (size_t)qi1 * HDIM + ks*16 + 2*t4);
        qa[ks][2] = *(const unsigned*)(Qb + (size_t)qi0 * HDIM + ks*16 + 2*t4 + 8);
        qa[ks][3] = *(const unsigned*)(Qb + (size_t)qi1 * HDIM + ks*16 + 2*t4 + 8);
    }

    float o[8][4];
    #pragma unroll
    for (int hf = 0; hf < 8; hf++)
        #pragma unroll
        for (int r = 0; r < 4; r++) o[hf][r] = 0.f;

    float mrow0 = -CUDART_INF_F, mrow1 = -CUDART_INF_F;
    float lrow0 = 0.f, lrow1 = 0.f;

    int qkRowL = (lane & 7) + ((lane & 16) ? 8 : 0);
    int qkColL = (lane & 8) ? 8 : 0;
    int pvRowL = (lane & 7) + ((lane & 8) ? 8 : 0);
    int pvColL = (lane & 16) ? 8 : 0;

    int kvRow[2], kvCol[2];
    #pragma unroll
    for (int j = 0; j < 2; j++) {
        int idx = tid + j * 256;
        kvRow[j] = idx >> 3; kvCol[j] = (idx & 7) * 8;
    }

    auto stage = [&](int buf, int kc) {
        #pragma unroll
        for (int j = 0; j < 2; j++) {
            cp16(sK + ((buf*64 + kvRow[j]) * 72 + kvCol[j]) * 2,
                 Kb + (size_t)(kc*64 + kvRow[j]) * HDIM + kvCol[j]);
            cp16(sV + ((buf*64 + kvRow[j]) * 72 + kvCol[j]) * 2,
                 Vb + (size_t)(kc*64 + kvRow[j]) * HDIM + kvCol[j]);
        }
        CP_COMMIT();
    };

    stage(0, 0);

    for (int kc = 0; kc < 16; kc++) {
        int cur = kc & 1;
        CP_WAIT0();
        __syncthreads();
        if (kc + 1 < 16) stage(cur ^ 1, kc + 1);

        // S = Q @ K^T   (16 x 64 per warp) ; scores are in log2 units
        float s[8][4];
        #pragma unroll
        for (int nf = 0; nf < 8; nf++)
            #pragma unroll
            for (int r = 0; r < 4; r++) s[nf][r] = 0.f;

        #pragma unroll
        for (int ks = 0; ks < 4; ks++) {
            #pragma unroll
            for (int nfp = 0; nfp < 4; nfp++) {
                unsigned b0, b1, b2, b3;
                unsigned addr = sK + ((cur*64 + nfp*16 + qkRowL) * 72 + ks*16 + qkColL) * 2;
                ldsm_x4(b0, b1, b2, b3, addr);
                unsigned bb0[2] = { b0, b1 }, bb1[2] = { b2, b3 };
                mma_f16(s[nfp*2    ], qa[ks], bb0);
                mma_f16(s[nfp*2 + 1], qa[ks], bb1);
            }
        }

        // dense bias (log2e-scaled) + online softmax in exp2 domain
        float mn0 = mrow0, mn1 = mrow1;
        #pragma unroll
        for (int nf = 0; nf < 8; nf++) {
            int off = kc*64 + nf*8;
            float2 b0 = __half22float2(*(const __half2*)(bQ0 + off));
            float2 b1 = __half22float2(*(const __half2*)(bQ1 + off));
            s[nf][0] += b0.x; s[nf][1] += b0.y;
            s[nf][2] += b1.x; s[nf][3] += b1.y;
            mn0 = fmaxf(mn0, fmaxf(s[nf][0], s[nf][1]));
            mn1 = fmaxf(mn1, fmaxf(s[nf][2], s[nf][3]));
        }
        mn0 = fmaxf(mn0, __shfl_xor_sync(0xffffffffu, mn0, 1));
        mn0 = fmaxf(mn0, __shfl_xor_sync(0xffffffffu, mn0, 2));
        mn1 = fmaxf(mn1, __shfl_xor_sync(0xffffffffu, mn1, 1));
        mn1 = fmaxf(mn1, __shfl_xor_sync(0xffffffffu, mn1, 2));

        float alpha0 = fexp2(mrow0 - mn0);
        float alpha1 = fexp2(mrow1 - mn1);
        mrow0 = mn0; mrow1 = mn1;

        float rs0 = 0.f, rs1 = 0.f;
        #pragma unroll
        for (int nf = 0; nf < 8; nf++) {
            #pragma unroll
            for (int r = 0; r < 4; r++) {
                float p = fexp2(s[nf][r] - ((r < 2) ? mn0 : mn1));
                s[nf][r] = p;
                if (r < 2) rs0 += p; else rs1 += p;
            }
        }
        rs0 += __shfl_xor_sync(0xffffffffu, rs0, 1);
        rs0 += __shfl_xor_sync(0xffffffffu, rs0, 2);
        rs1 += __shfl_xor_sync(0xffffffffu, rs1, 1);
        rs1 += __shfl_xor_sync(0xffffffffu, rs1, 2);
        lrow0 = lrow0 * alpha0 + rs0;
        lrow1 = lrow1 * alpha1 + rs1;

        #pragma unroll
        for (int hf = 0; hf < 8; hf++) {
            o[hf][0] *= alpha0; o[hf][1] *= alpha0;
            o[hf][2] *= alpha1; o[hf][3] *= alpha1;
        }

        // O += P @ V ; A-frags = repacked score c-frags
        #pragma unroll
        for (int ks = 0; ks < 4; ks++) {
            unsigned ap[4];
            ap[0] = h2u(__floats2half2_rn(s[2*ks  ][0], s[2*ks  ][1]));
            ap[1] = h2u(__floats2half2_rn(s[2*ks  ][2], s[2*ks  ][3]));
            ap[2] = h2u(__floats2half2_rn(s[2*ks+1][0], s[2*ks+1][1]));
            ap[3] = h2u(__floats2half2_rn(s[2*ks+1][2], s[2*ks+1][3]));
            #pragma unroll
            for (int hfp = 0; hfp < 4; hfp++) {
                unsigned v0, v1, v2, v3;
                unsigned addr = sV + ((cur*64 + ks*16 + pvRowL) * 72 + hfp*16 + pvColL) * 2;
                ldsm_x4_t(v0, v1, v2, v3, addr);
                unsigned vv0[2] = { v0, v1 }, vv1[2] = { v2, v3 };
                mma_f16(o[hfp*2    ], ap, vv0);
                mma_f16(o[hfp*2 + 1], ap, vv1);
            }
        }
    }

    float inv0 = 1.f / lrow0, inv1 = 1.f / lrow1;
    #pragma unroll
    for (int hf = 0; hf < 8; hf++) {
        int hd = hf*8 + t4*2;
        size_t base0 = ((size_t)b_ * SEQ + qi0) * DMODEL + h_ * HDIM + hd;
        size_t base1 = ((size_t)b_ * SEQ + qi1) * DMODEL + h_ * HDIM + hd;
        *(unsigned*)&g_Xh[base0] = h2u(__floats2half2_rn(o[hf][0] * inv0, o[hf][1] * inv0));
        *(unsigned*)&g_Xh[base1] = h2u(__floats2half2_rn(o[hf][2] * inv1, o[hf][3] * inv1));
    }
}

// ---------------- launcher -------------------------------------------------
extern "C" void kernel_launch(void* const* d_in, const int* in_sizes, int n_in,
                              void* d_out, int out_size) {
    const float* inputs_q  = (const float*)d_in[0];
    const float* inputs_kv = (const float*)d_in[1];
    const float* Wq = (const float*)d_in[2];
    const float* bq = (const float*)d_in[3];
    const float* Wk = (const float*)d_in[4];
    const float* bk = (const float*)d_in[5];
    const float* Wv = (const float*)d_in[6];
    const float* bv = (const float*)d_in[7];
    const float* Wo = (const float*)d_in[8];
    const float* bo = (const float*)d_in[9];
    const float* rel_bias = (const float*)d_in[10];
    // d_in[11] = pos : unused (index computed analytically in-kernel)
    float* out = (float*)d_out;

    transpose_bias<<<(TABLE * NH + 255) / 256, 256>>>(rel_bias);
    bias_expand<<<(NH * SEQ * (SEQ / 8) + 255) / 256, 256>>>();

    const int NIN4 = BATCH * SEQ * DMODEL / 4;     // 1,572,864
    f2h_inputs<<<dim3((NIN4 + 255) / 256, 2), 256>>>(inputs_q, inputs_kv, NIN4);
    f2h_weights<<<dim3((DD / 4 + 255) / 256, 4), 256>>>(Wq, Wk, Wv, Wo);

    dim3 gqkv(BATCH * SEQ / 128, 18);              // 64 x 18 (y/6 selects Q/K/V)
    gemm128<<<gqkv, 256>>>(bq, bk, bv, nullptr, 0);

    dim3 ga(SEQ / 128, BATCH * NH);                // 8 x 96
    attn_kernel<<<ga, 256>>>();

    dim3 gout(BATCH * SEQ / 128, DMODEL / 128);    // 64 x 6
    gemm128<<<gout, 256>>>(bo, nullptr, nullptr, out, 1);
}